// round 11
// baseline (speedup 1.0000x reference)
#include <cuda_runtime.h>
#include <cuda_bf16.h>
#include <cstdint>

// Problem dims (fixed by the reference)
#define BATCH   8
#define LSEQ    2048
#define DMODEL  768
#define DIN     1536
#define NHEADS  4
#define DHEAD   192
#define MROWS   (BATCH * LSEQ)   // 16384
#define NQKV    (3 * DMODEL)     // 2304

// ---------------------------------------------------------------------------
// Scratch (allocation-free rule: __device__ globals)
// ---------------------------------------------------------------------------
__device__ __nv_bfloat16 g_Ahi[MROWS * DIN];
__device__ __nv_bfloat16 g_Alo[MROWS * DIN];
__device__ __nv_bfloat16 g_Wqkv_hi[NQKV * DIN];    // [n][k] K-major
__device__ __nv_bfloat16 g_Wqkv_lo[NQKV * DIN];
__device__ __nv_bfloat16 g_Wo_hi[DMODEL * DMODEL]; // [n][k] K-major
__device__ __nv_bfloat16 g_Wo_lo[DMODEL * DMODEL];
__device__ float g_bqkv[NQKV];
__device__ __nv_bfloat16 g_Qh[MROWS * DMODEL];
__device__ __nv_bfloat16 g_Ql[MROWS * DMODEL];
__device__ __nv_bfloat16 g_Kh[MROWS * DMODEL];
__device__ __nv_bfloat16 g_Kl[MROWS * DMODEL];
__device__ __nv_bfloat16 g_Vh[MROWS * DMODEL];
__device__ __nv_bfloat16 g_Vl[MROWS * DMODEL];
__device__ __nv_bfloat16 g_Chi[MROWS * DMODEL];
__device__ __nv_bfloat16 g_Clo[MROWS * DMODEL];

// ---------------------------------------------------------------------------
// Base-ISA helpers
// ---------------------------------------------------------------------------
__device__ __forceinline__ uint32_t smem_to_u32(const void* p) {
    uint32_t a;
    asm("{ .reg .u64 t; cvta.to.shared.u64 t, %1; cvt.u32.u64 %0, t; }"
        : "=r"(a) : "l"(p));
    return a;
}
__device__ __forceinline__ void ldsm4(uint32_t* r, uint32_t addr) {
    asm volatile("ldmatrix.sync.aligned.m8n8.x4.shared.b16 {%0,%1,%2,%3}, [%4];"
                 : "=r"(r[0]), "=r"(r[1]), "=r"(r[2]), "=r"(r[3]) : "r"(addr));
}
__device__ __forceinline__ void ldsm4t(uint32_t* r, uint32_t addr) {
    asm volatile("ldmatrix.sync.aligned.m8n8.x4.trans.shared.b16 {%0,%1,%2,%3}, [%4];"
                 : "=r"(r[0]), "=r"(r[1]), "=r"(r[2]), "=r"(r[3]) : "r"(addr));
}
__device__ __forceinline__ void mma_bf16(float* c, const uint32_t* a, const uint32_t* b) {
    asm volatile(
        "mma.sync.aligned.m16n8k16.row.col.f32.bf16.bf16.f32 "
        "{%0,%1,%2,%3}, {%4,%5,%6,%7}, {%8,%9}, {%0,%1,%2,%3};"
        : "+f"(c[0]), "+f"(c[1]), "+f"(c[2]), "+f"(c[3])
        : "r"(a[0]), "r"(a[1]), "r"(a[2]), "r"(a[3]), "r"(b[0]), "r"(b[1]));
}
__device__ __forceinline__ void cpasync16(uint32_t saddr, const void* g) {
    asm volatile("cp.async.cg.shared.global [%0], [%1], 16;" :: "r"(saddr), "l"(g));
}
#define CP_COMMIT() asm volatile("cp.async.commit_group;" ::: "memory")
#define CP_WAIT1()  asm volatile("cp.async.wait_group 1;" ::: "memory")

__device__ __forceinline__ void split_bf16(float v, __nv_bfloat16& h, __nv_bfloat16& l) {
    h = __float2bfloat16(v);
    l = __float2bfloat16(v - __bfloat162float(h));
}
__device__ __forceinline__ uint32_t pack2(__nv_bfloat16 a, __nv_bfloat16 b) {
    __nv_bfloat162 t = __halves2bfloat162(a, b);
    return *(uint32_t*)&t;
}

// ---------------------------------------------------------------------------
// Preprocessing (all coalesced)
// ---------------------------------------------------------------------------
__global__ void conv_samples(const float4* __restrict__ src, int n4) {
    int i = blockIdx.x * 256 + threadIdx.x;
    if (i >= n4) return;
    float4 v = src[i];
    __nv_bfloat16 h0, h1, h2, h3, l0, l1, l2, l3;
    split_bf16(v.x, h0, l0); split_bf16(v.y, h1, l1);
    split_bf16(v.z, h2, l2); split_bf16(v.w, h3, l3);
    *(__nv_bfloat162*)(g_Ahi + 4 * (size_t)i)     = __halves2bfloat162(h0, h1);
    *(__nv_bfloat162*)(g_Ahi + 4 * (size_t)i + 2) = __halves2bfloat162(h2, h3);
    *(__nv_bfloat162*)(g_Alo + 4 * (size_t)i)     = __halves2bfloat162(l0, l1);
    *(__nv_bfloat162*)(g_Alo + 4 * (size_t)i + 2) = __halves2bfloat162(l2, l3);
}

// Tile-transpose W[K][N] -> out[n][k] hi/lo, coalesced both directions.
__global__ void conv_wqkv_t(const float* __restrict__ Wq, const float* __restrict__ Wk,
                            const float* __restrict__ Wv) {
    __shared__ float t[32][33];
    const int mat = blockIdx.z;
    const float* W = (mat == 0) ? Wq : (mat == 1) ? Wk : Wv;
    const int n0 = blockIdx.x * 32, k0 = blockIdx.y * 32;
    const int tx = threadIdx.x, ty = threadIdx.y;
#pragma unroll
    for (int r = 0; r < 32; r += 8)
        t[ty + r][tx] = W[(size_t)(k0 + ty + r) * DMODEL + n0 + tx];
    __syncthreads();
#pragma unroll
    for (int r = 0; r < 32; r += 8) {
        float v = t[tx][ty + r];           // = W[k0+tx][n0+ty+r]
        __nv_bfloat16 h, l; split_bf16(v, h, l);
        size_t o = (size_t)(mat * DMODEL + n0 + ty + r) * DIN + k0 + tx;
        g_Wqkv_hi[o] = h; g_Wqkv_lo[o] = l;
    }
}

__global__ void conv_wo_t(const float* __restrict__ Wo) {
    __shared__ float t[32][33];
    const int n0 = blockIdx.x * 32, k0 = blockIdx.y * 32;
    const int tx = threadIdx.x, ty = threadIdx.y;
#pragma unroll
    for (int r = 0; r < 32; r += 8)
        t[ty + r][tx] = Wo[(size_t)(k0 + ty + r) * DMODEL + n0 + tx];
    __syncthreads();
#pragma unroll
    for (int r = 0; r < 32; r += 8) {
        float v = t[tx][ty + r];
        __nv_bfloat16 h, l; split_bf16(v, h, l);
        size_t o = (size_t)(n0 + ty + r) * DMODEL + k0 + tx;
        g_Wo_hi[o] = h; g_Wo_lo[o] = l;
    }
}

__global__ void conv_bias(const float* __restrict__ bq, const float* __restrict__ bk,
                          const float* __restrict__ bv) {
    int i = blockIdx.x * 256 + threadIdx.x;
    if (i < NQKV)
        g_bqkv[i] = (i < DMODEL) ? bq[i] : (i < 2 * DMODEL) ? bk[i - DMODEL] : bv[i - 2 * DMODEL];
}

// ---------------------------------------------------------------------------
// mma.sync split-bf16 GEMM: C[M,N] = A[M,K] @ W[K,N] + bias
// 2-stage cp.async pipeline (80KB smem), 2 CTAs/SM. B frags resident,
// A frags streamed per-mf to stay under 128 regs.
// ---------------------------------------------------------------------------
#define TROW    40
#define TILE_B  (128 * TROW * 2)
#define STAGE_B (4 * TILE_B)
#define NSTAGE  2
#define GEMM_SMEM (NSTAGE * STAGE_B)     // 81920

__device__ __forceinline__ void issue_stage(
    uint32_t sbase, const __nv_bfloat16* __restrict__ Ah,
    const __nv_bfloat16* __restrict__ Al, const __nv_bfloat16* __restrict__ Bh,
    const __nv_bfloat16* __restrict__ Bl, int row0, int n0g, int k0, int K, int tid) {
    const __nv_bfloat16* srcs[4] = {Ah, Al, Bh, Bl};
#pragma unroll
    for (int t = 0; t < 8; t++) {
        int c    = tid + t * 256;
        int tile = c >> 9;
        int idx  = c & 511;
        int row  = idx >> 2;
        int kc   = (idx & 3) * 8;
        int grow = ((tile < 2) ? row0 : n0g) + row;
        const __nv_bfloat16* g = srcs[tile] + (size_t)grow * K + k0 + kc;
        uint32_t saddr = sbase + tile * TILE_B + (uint32_t)(row * TROW + kc) * 2;
        cpasync16(saddr, g);
    }
}

template <bool BF16OUT>
__global__ __launch_bounds__(256, 2)
void gemm_hilo(const __nv_bfloat16* __restrict__ Ah, const __nv_bfloat16* __restrict__ Al,
               const __nv_bfloat16* __restrict__ Bh, const __nv_bfloat16* __restrict__ Bl,
               const float* __restrict__ bias, float* outF,
               __nv_bfloat16* o0h, __nv_bfloat16* o0l,
               __nv_bfloat16* o1h, __nv_bfloat16* o1l,
               __nv_bfloat16* o2h, __nv_bfloat16* o2l,
               int K, int Nout, int ntpm) {
    extern __shared__ char smem[];
    const uint32_t smem_u = smem_to_u32(smem);
    const int tid  = threadIdx.x;
    const int lane = tid & 31;
    const int wid  = tid >> 5;
    const int bx = blockIdx.x, by = blockIdx.y;

    const int mat = bx / ntpm;
    const int row0 = by * 128;
    const int n0g  = bx * 128;
    const int n0   = (bx % ntpm) * 128;

    const int wm = wid >> 2;
    const int wn = wid & 3;
    const int ns = K / 32;

    issue_stage(smem_u, Ah, Al, Bh, Bl, row0, n0g, 0, K, tid);
    CP_COMMIT();
    issue_stage(smem_u + STAGE_B, Ah, Al, Bh, Bl, row0, n0g, 32, K, tid);
    CP_COMMIT();

    float c[4][4][4];
#pragma unroll
    for (int i = 0; i < 4; i++)
#pragma unroll
        for (int j = 0; j < 4; j++)
#pragma unroll
            for (int q = 0; q < 4; q++) c[i][j][q] = 0.f;

    const int a_row = lane & 15;
    const int a_kad = (lane >> 4) * 8;
    const int b_r   = lane & 7;
    const int b_q   = lane >> 3;
    const int b_nad = (b_q >> 1) * 8;
    const int b_kad = (b_q & 1) * 8;

    for (int s = 0; s < ns; s++) {
        CP_WAIT1();
        __syncthreads();

        const uint32_t sb  = smem_u + (s & 1) * STAGE_B;
        const uint32_t sAh = sb;
        const uint32_t sAl = sb + TILE_B;
        const uint32_t sBh = sb + 2 * TILE_B;
        const uint32_t sBl = sb + 3 * TILE_B;

#pragma unroll
        for (int ks = 0; ks < 2; ks++) {
            uint32_t bh[2][4], bl[2][4];
#pragma unroll
            for (int np = 0; np < 2; np++) {
                uint32_t off = ((uint32_t)((wn * 32 + np * 16 + b_r + b_nad) * TROW
                                           + ks * 16 + b_kad)) * 2;
                ldsm4(bh[np], sBh + off);
                ldsm4(bl[np], sBl + off);
            }
#pragma unroll
            for (int mf = 0; mf < 4; mf++) {
                uint32_t ah[4], al[4];
                uint32_t off = ((uint32_t)((wm * 64 + mf * 16 + a_row) * TROW
                                           + ks * 16 + a_kad)) * 2;
                ldsm4(ah, sAh + off);
                ldsm4(al, sAl + off);
#pragma unroll
                for (int nf = 0; nf < 4; nf++) {
                    const int np = nf >> 1, bo = (nf & 1) * 2;
                    mma_bf16(c[mf][nf], ah, &bh[np][bo]);
                    mma_bf16(c[mf][nf], ah, &bl[np][bo]);
                    mma_bf16(c[mf][nf], al, &bh[np][bo]);
                }
            }
        }
        __syncthreads();
        if (s + 2 < ns)
            issue_stage(sb, Ah, Al, Bh, Bl, row0, n0g, (s + 2) * 32, K, tid);
        CP_COMMIT();
    }

    const int g  = lane >> 2;
    const int tg = lane & 3;
#pragma unroll
    for (int nf = 0; nf < 4; nf++) {
        const int colL = wn * 32 + nf * 8 + 2 * tg;
        const float b0 = bias[n0g + colL];
        const float b1 = bias[n0g + colL + 1];
#pragma unroll
        for (int mf = 0; mf < 4; mf++) {
            const int row = row0 + wm * 64 + mf * 16 + g;
            float f0 = c[mf][nf][0] + b0, f1 = c[mf][nf][1] + b1;
            float f2 = c[mf][nf][2] + b0, f3 = c[mf][nf][3] + b1;
            if (BF16OUT) {
                __nv_bfloat16* oh = (mat == 0) ? o0h : (mat == 1) ? o1h : o2h;
                __nv_bfloat16* ol = (mat == 0) ? o0l : (mat == 1) ? o1l : o2l;
                __nv_bfloat16 h0, h1, h2, h3, e0, e1, e2, e3;
                split_bf16(f0, h0, e0); split_bf16(f1, h1, e1);
                split_bf16(f2, h2, e2); split_bf16(f3, h3, e3);
                size_t p0 = (size_t)row * Nout + n0 + colL;
                size_t p1 = (size_t)(row + 8) * Nout + n0 + colL;
                *(__nv_bfloat162*)(oh + p0) = __halves2bfloat162(h0, h1);
                *(__nv_bfloat162*)(ol + p0) = __halves2bfloat162(e0, e1);
                *(__nv_bfloat162*)(oh + p1) = __halves2bfloat162(h2, h3);
                *(__nv_bfloat162*)(ol + p1) = __halves2bfloat162(e2, e3);
            } else {
                *(float2*)(outF + (size_t)row * Nout + n0 + colL)       = {f0, f1};
                *(float2*)(outF + (size_t)(row + 8) * Nout + n0 + colL) = {f2, f3};
            }
        }
    }
}

// ---------------------------------------------------------------------------
// Tensor-core flash attention (hi/lo bf16, fp32 accum, online softmax).
// ---------------------------------------------------------------------------
#define AROW      200
#define AQ_BYTES  (128 * AROW * 2)
#define KV_TILE_B (32 * AROW * 2)
#define STAGE_AB  (4 * KV_TILE_B)
#define ATTN_SMEM (2 * AQ_BYTES + 2 * STAGE_AB)
#define NKT       (LSEQ / 32)

__global__ __launch_bounds__(256, 1)
void attn_mma(const __nv_bfloat16* __restrict__ Qh, const __nv_bfloat16* __restrict__ Ql,
              const __nv_bfloat16* __restrict__ Kh, const __nv_bfloat16* __restrict__ Kl,
              const __nv_bfloat16* __restrict__ Vh, const __nv_bfloat16* __restrict__ Vl) {
    extern __shared__ char sm[];
    const uint32_t su = smem_to_u32(sm);
    const uint32_t sQh = su, sQl = su + AQ_BYTES;
    const uint32_t sStage = su + 2 * AQ_BYTES;

    const int tid = threadIdx.x, wid = tid >> 5, lane = tid & 31;
    const int qtile = blockIdx.x, bh = blockIdx.y;
    const int b = bh / NHEADS, h = bh % NHEADS;
    const size_t gbase = (size_t)b * LSEQ * DMODEL + h * DHEAD;

    const __nv_bfloat16* Qgh = Qh + gbase + (size_t)qtile * 128 * DMODEL;
    const __nv_bfloat16* Qgl = Ql + gbase + (size_t)qtile * 128 * DMODEL;
    const __nv_bfloat16* Kgh = Kh + gbase;
    const __nv_bfloat16* Kgl = Kl + gbase;
    const __nv_bfloat16* Vgh = Vh + gbase;
    const __nv_bfloat16* Vgl = Vl + gbase;

    for (int i = tid; i < 2 * 3072; i += 256) {
        int tz = i / 3072, idx = i % 3072;
        int r = idx / 24, cc = (idx % 24) * 8;
        const __nv_bfloat16* src = (tz ? Qgl : Qgh) + (size_t)r * DMODEL + cc;
        uint4 v = *(const uint4*)src;
        *(uint4*)(sm + (tz ? AQ_BYTES : 0) + r * 400 + cc * 2) = v;
    }

    const __nv_bfloat16* kvsrc[4] = {Kgh, Kgl, Vgh, Vgl};
#pragma unroll
    for (int st = 0; st < 2; st++) {
        uint32_t sb = sStage + st * STAGE_AB;
#pragma unroll
        for (int j = 0; j < 12; j++) {
            int i = tid + j * 256;
            int tz = i / 768, idx = i % 768;
            int r = idx / 24, cc = (idx % 24) * 8;
            cpasync16(sb + tz * KV_TILE_B + (uint32_t)(r * 400 + cc * 2),
                      kvsrc[tz] + (size_t)(st * 32 + r) * DMODEL + cc);
        }
        CP_COMMIT();
    }
    __syncthreads();

    const int a_row = lane & 15;
    const int a_k   = (lane >> 4) * 8;
    const int b_r   = lane & 7;
    const int b_q   = lane >> 3;
    const int b_n   = (b_q >> 1) * 8;
    const int b_k   = (b_q & 1) * 8;

    float O[24][4];
#pragma unroll
    for (int i = 0; i < 24; i++)
#pragma unroll
        for (int j = 0; j < 4; j++) O[i][j] = 0.f;
    float m_lo = -1e30f, m_hi = -1e30f, l_lo = 0.f, l_hi = 0.f;

    for (int t = 0; t < NKT; t++) {
        CP_WAIT1();
        __syncthreads();
        const uint32_t sb  = sStage + (t & 1) * STAGE_AB;
        const uint32_t sKh = sb, sKl = sb + KV_TILE_B;
        const uint32_t sVh = sb + 2 * KV_TILE_B, sVl = sb + 3 * KV_TILE_B;

        float S[4][4];
#pragma unroll
        for (int i = 0; i < 4; i++)
#pragma unroll
            for (int j = 0; j < 4; j++) S[i][j] = 0.f;

#pragma unroll
        for (int kc = 0; kc < 12; kc++) {
            uint32_t qh[4], ql[4], kh[2][4], kl[2][4];
            uint32_t qoff = (uint32_t)((wid * 16 + a_row) * 200 + kc * 16 + a_k) * 2;
            ldsm4(qh, sQh + qoff);
            ldsm4(ql, sQl + qoff);
#pragma unroll
            for (int np = 0; np < 2; np++) {
                uint32_t koff = (uint32_t)((np * 16 + b_r + b_n) * 200 + kc * 16 + b_k) * 2;
                ldsm4(kh[np], sKh + koff);
                ldsm4(kl[np], sKl + koff);
            }
#pragma unroll
            for (int nf = 0; nf < 4; nf++) {
                const uint32_t* bhf = &kh[nf >> 1][(nf & 1) * 2];
                const uint32_t* blf = &kl[nf >> 1][(nf & 1) * 2];
                mma_bf16(S[nf], qh, bhf);
                mma_bf16(S[nf], qh, blf);
                mma_bf16(S[nf], ql, bhf);
            }
        }

        float mx0 = fmaxf(fmaxf(S[0][0], S[0][1]), fmaxf(S[1][0], S[1][1]));
        mx0 = fmaxf(mx0, fmaxf(fmaxf(S[2][0], S[2][1]), fmaxf(S[3][0], S[3][1])));
        float mx1 = fmaxf(fmaxf(S[0][2], S[0][3]), fmaxf(S[1][2], S[1][3]));
        mx1 = fmaxf(mx1, fmaxf(fmaxf(S[2][2], S[2][3]), fmaxf(S[3][2], S[3][3])));
        mx0 = fmaxf(mx0, __shfl_xor_sync(0xffffffffu, mx0, 1));
        mx0 = fmaxf(mx0, __shfl_xor_sync(0xffffffffu, mx0, 2));
        mx1 = fmaxf(mx1, __shfl_xor_sync(0xffffffffu, mx1, 1));
        mx1 = fmaxf(mx1, __shfl_xor_sync(0xffffffffu, mx1, 2));
        float mn0 = fmaxf(m_lo, mx0), mn1 = fmaxf(m_hi, mx1);
        float a0 = __expf(m_lo - mn0), a1 = __expf(m_hi - mn1);
        m_lo = mn0; m_hi = mn1;

        float s0 = 0.f, s1 = 0.f;
#pragma unroll
        for (int nf = 0; nf < 4; nf++) {
            S[nf][0] = __expf(S[nf][0] - m_lo);
            S[nf][1] = __expf(S[nf][1] - m_lo);
            S[nf][2] = __expf(S[nf][2] - m_hi);
            S[nf][3] = __expf(S[nf][3] - m_hi);
            s0 += S[nf][0] + S[nf][1];
            s1 += S[nf][2] + S[nf][3];
        }
        s0 += __shfl_xor_sync(0xffffffffu, s0, 1);
        s0 += __shfl_xor_sync(0xffffffffu, s0, 2);
        s1 += __shfl_xor_sync(0xffffffffu, s1, 1);
        s1 += __shfl_xor_sync(0xffffffffu, s1, 2);
        l_lo = l_lo * a0 + s0;
        l_hi = l_hi * a1 + s1;

        if (__ballot_sync(0xffffffffu, (a0 != 1.f) || (a1 != 1.f))) {
#pragma unroll
            for (int nf = 0; nf < 24; nf++) {
                O[nf][0] *= a0; O[nf][1] *= a0;
                O[nf][2] *= a1; O[nf][3] *= a1;
            }
        }

#pragma unroll
        for (int kc2 = 0; kc2 < 2; kc2++) {
            uint32_t ah[4], al[4];
#pragma unroll
            for (int r = 0; r < 4; r++) {
                const int f = 2 * kc2 + (r >> 1);
                const int c0 = (r & 1) * 2;
                __nv_bfloat16 h0, h1, e0, e1;
                split_bf16(S[f][c0], h0, e0);
                split_bf16(S[f][c0 + 1], h1, e1);
                ah[r] = pack2(h0, h1);
                al[r] = pack2(e0, e1);
            }
#pragma unroll
            for (int nb = 0; nb < 12; nb++) {
                uint32_t vh[4], vl[4];
                uint32_t voff = (uint32_t)((kc2 * 16 + a_row) * 200 + nb * 16 + a_k) * 2;
                ldsm4t(vh, sVh + voff);
                ldsm4t(vl, sVl + voff);
                mma_bf16(O[2 * nb],     ah, &vh[0]);
                mma_bf16(O[2 * nb],     ah, &vl[0]);
                mma_bf16(O[2 * nb],     al, &vh[0]);
                mma_bf16(O[2 * nb + 1], ah, &vh[2]);
                mma_bf16(O[2 * nb + 1], ah, &vl[2]);
                mma_bf16(O[2 * nb + 1], al, &vh[2]);
            }
        }

        __syncthreads();
        if (t + 2 < NKT) {
            uint32_t nb2 = sStage + (t & 1) * STAGE_AB;
#pragma unroll
            for (int j = 0; j < 12; j++) {
                int i = tid + j * 256;
                int tz = i / 768, idx = i % 768;
                int r = idx / 24, cc = (idx % 24) * 8;
                cpasync16(nb2 + tz * KV_TILE_B + (uint32_t)(r * 400 + cc * 2),
                          kvsrc[tz] + (size_t)((t + 2) * 32 + r) * DMODEL + cc);
            }
        }
        CP_COMMIT();
    }

    const float i0 = 1.f / l_lo, i1 = 1.f / l_hi;
    const int row = qtile * 128 + wid * 16 + (lane >> 2);
    const int colb = h * DHEAD + (lane & 3) * 2;
#pragma unroll
    for (int nf = 0; nf < 24; nf++) {
        const int col = colb + nf * 8;
        float f0 = O[nf][0] * i0, f1 = O[nf][1] * i0;
        float f2 = O[nf][2] * i1, f3 = O[nf][3] * i1;
        __nv_bfloat16 h0, h1, h2, h3, e0, e1, e2, e3;
        split_bf16(f0, h0, e0); split_bf16(f1, h1, e1);
        split_bf16(f2, h2, e2); split_bf16(f3, h3, e3);
        size_t p0 = ((size_t)b * LSEQ + row) * DMODEL + col;
        size_t p1 = ((size_t)b * LSEQ + row + 8) * DMODEL + col;
        *(__nv_bfloat162*)(g_Chi + p0) = __halves2bfloat162(h0, h1);
        *(__nv_bfloat162*)(g_Clo + p0) = __halves2bfloat162(e0, e1);
        *(__nv_bfloat162*)(g_Chi + p1) = __halves2bfloat162(h2, h3);
        *(__nv_bfloat162*)(g_Clo + p1) = __halves2bfloat162(e2, e3);
    }
}

// ---------------------------------------------------------------------------
// Launch
// ---------------------------------------------------------------------------
extern "C" void kernel_launch(void* const* d_in, const int* in_sizes, int n_in,
                              void* d_out, int out_size) {
    const float* samples = (const float*)d_in[0];
    const float* Wq = (const float*)d_in[1];
    const float* bq = (const float*)d_in[2];
    const float* Wk = (const float*)d_in[3];
    const float* bk = (const float*)d_in[4];
    const float* Wv = (const float*)d_in[5];
    const float* bv = (const float*)d_in[6];
    const float* Wo = (const float*)d_in[7];
    const float* bo = (const float*)d_in[8];

    float* bqkv;
    __nv_bfloat16 *Ahi, *Alo, *Wqh, *Wql, *Woh, *Wol, *Chi, *Clo;
    __nv_bfloat16 *Qhp, *Qlp, *Khp, *Klp, *Vhp, *Vlp;
    cudaGetSymbolAddress((void**)&bqkv, g_bqkv);
    cudaGetSymbolAddress((void**)&Ahi,  g_Ahi);
    cudaGetSymbolAddress((void**)&Alo,  g_Alo);
    cudaGetSymbolAddress((void**)&Wqh,  g_Wqkv_hi);
    cudaGetSymbolAddress((void**)&Wql,  g_Wqkv_lo);
    cudaGetSymbolAddress((void**)&Woh,  g_Wo_hi);
    cudaGetSymbolAddress((void**)&Wol,  g_Wo_lo);
    cudaGetSymbolAddress((void**)&Chi,  g_Chi);
    cudaGetSymbolAddress((void**)&Clo,  g_Clo);
    cudaGetSymbolAddress((void**)&Qhp,  g_Qh);
    cudaGetSymbolAddress((void**)&Qlp,  g_Ql);
    cudaGetSymbolAddress((void**)&Khp,  g_Kh);
    cudaGetSymbolAddress((void**)&Klp,  g_Kl);
    cudaGetSymbolAddress((void**)&Vhp,  g_Vh);
    cudaGetSymbolAddress((void**)&Vlp,  g_Vl);

    {
        int n4 = MROWS * DIN / 4;
        conv_samples<<<(n4 + 255) / 256, 256>>>((const float4*)samples, n4);
        conv_wqkv_t<<<dim3(DMODEL / 32, DIN / 32, 3), dim3(32, 8)>>>(Wq, Wk, Wv);
        conv_wo_t<<<dim3(DMODEL / 32, DMODEL / 32), dim3(32, 8)>>>(Wo);
        conv_bias<<<(NQKV + 255) / 256, 256>>>(bq, bk, bv);
    }

    cudaFuncSetAttribute(gemm_hilo<true>,  cudaFuncAttributeMaxDynamicSharedMemorySize, GEMM_SMEM);
    cudaFuncSetAttribute(gemm_hilo<false>, cudaFuncAttributeMaxDynamicSharedMemorySize, GEMM_SMEM);
    cudaFuncSetAttribute(attn_mma, cudaFuncAttributeMaxDynamicSharedMemorySize, ATTN_SMEM);

    // Fused QKV projection -> (hi,lo) bf16 Q,K,V
    gemm_hilo<true><<<dim3(NQKV / 128, MROWS / 128), 256, GEMM_SMEM>>>(
        Ahi, Alo, Wqh, Wql, bqkv, nullptr,
        Qhp, Qlp, Khp, Klp, Vhp, Vlp, DIN, DMODEL, DMODEL / 128);

    // Tensor-core flash attention
    attn_mma<<<dim3(LSEQ / 128, BATCH * NHEADS), 256, ATTN_SMEM>>>(
        Qhp, Qlp, Khp, Klp, Vhp, Vlp);

    // Output projection -> fp32 d_out
    gemm_hilo<false><<<dim3(DMODEL / 128, MROWS / 128), 256, GEMM_SMEM>>>(
        Chi, Clo, Woh, Wol, bo, (float*)d_out,
        nullptr, nullptr, nullptr, nullptr, nullptr, nullptr,
        DMODEL, DMODEL, DMODEL / 128);
}